// round 5
// baseline (speedup 1.0000x reference)
#include <cuda_runtime.h>
#include <cuda_bf16.h>
#include <cstdint>

// PairwiseRepresentation: masked periodic pairwise distances.
//   positions      [B,N,3]   f32
//   neighbors      [B,N,K]   i32
//   neighbor_mask  [B,N,K]   f32
//   cell           [B,3,3]   f32
//   cell_offsets   [B,N,K,3] f32
//   out            [B,N,K]   f32
//
// R5: back to 256-thread CTAs / 3 CTAs per SM (no register squeeze), and the
// row loop is unrolled x2 per warp: all 10 streaming LDGs for two rows are
// issued before either row is consumed, doubling per-warp MLP (the R4
// post-mortem showed the kernel is dependency-chain bound, not warp-bound).

#define MAX_ROWS (16 * 4096)
__device__ float4 g_pos4[MAX_ROWS];   // scratch for the fallback path only

__global__ __launch_bounds__(256)
void pad_positions_kernel(const float* __restrict__ positions, int n_rows)
{
    int i = blockIdx.x * blockDim.x + threadIdx.x;
    if (i < n_rows && i < MAX_ROWS) {
        g_pos4[i] = make_float4(positions[i * 3 + 0],
                                positions[i * 3 + 1],
                                positions[i * 3 + 2], 0.0f);
    }
}

// ---------------- main kernel: smem position table, 2-row pipeline ----------
__global__ __launch_bounds__(256, 3)
void pairwise_smem_kernel(const float*  __restrict__ positions,
                          const int*    __restrict__ neighbors,
                          const float*  __restrict__ mask,
                          const float*  __restrict__ cell,
                          const float*  __restrict__ offsets,
                          float*        __restrict__ out,
                          int N, int K, int rowsPer)
{
    extern __shared__ float4 s_tab[];          // N float4s (64KB for N=4096)

    const int b = blockIdx.y;

    // Fused pad + table fill: read [N,3] f32 coalesced, write float4 smem.
    const float* pb = positions + (size_t)b * N * 3;
    for (int i = threadIdx.x; i < N; i += blockDim.x)
        s_tab[i] = make_float4(__ldg(&pb[i * 3 + 0]),
                               __ldg(&pb[i * 3 + 1]),
                               __ldg(&pb[i * 3 + 2]), 0.0f);

    // Per-batch cell matrix -> registers.
    const float* cb = cell + b * 9;
    const float c00 = __ldg(&cb[0]), c01 = __ldg(&cb[1]), c02 = __ldg(&cb[2]);
    const float c10 = __ldg(&cb[3]), c11 = __ldg(&cb[4]), c12 = __ldg(&cb[5]);
    const float c20 = __ldg(&cb[6]), c21 = __ldg(&cb[7]), c22 = __ldg(&cb[8]);

    __syncthreads();

    const int warp    = threadIdx.x >> 5;      // 0..7
    const int lane    = threadIdx.x & 31;
    const int n_warps = blockDim.x >> 5;       // 8

    const int r0 = blockIdx.x * rowsPer;
    const int r1 = min(r0 + rowsPer, N);

    // Fast path: one 128-wide chunk covers K (K==128).
    if (K == 128) {
        int r = r0 + 2 * warp;
        // --- paired rows: 10 LDGs in flight before any consumption ---
        for (; r + 1 < r1; r += 2 * n_warps) {
            const long baseA = ((long)b * N + r)     * 128 + lane * 4;
            const long baseB = ((long)b * N + r + 1) * 128 + lane * 4;

            const int4   nbA = __ldcs((const int4*)  (neighbors + baseA));
            const int4   nbB = __ldcs((const int4*)  (neighbors + baseB));
            const float4 mkA = __ldcs((const float4*)(mask      + baseA));
            const float4 mkB = __ldcs((const float4*)(mask      + baseB));

            const float* opA = offsets + baseA * 3;
            const float* opB = offsets + baseB * 3;
            const float4 a0 = __ldcs((const float4*)(opA + 0));
            const float4 a1 = __ldcs((const float4*)(opA + 4));
            const float4 a2 = __ldcs((const float4*)(opA + 8));
            const float4 b0 = __ldcs((const float4*)(opB + 0));
            const float4 b1 = __ldcs((const float4*)(opB + 4));
            const float4 b2 = __ldcs((const float4*)(opB + 8));

            const float4 piA = s_tab[r];
            const float4 piB = s_tab[r + 1];

            // --- row A ---
            {
                const int   jj[4] = { nbA.x, nbA.y, nbA.z, nbA.w };
                const float ox[4] = { a0.x, a0.w, a1.z, a2.y };
                const float oy[4] = { a0.y, a1.x, a1.w, a2.z };
                const float oz[4] = { a0.z, a1.y, a2.x, a2.w };
                const float mm[4] = { mkA.x, mkA.y, mkA.z, mkA.w };
                float4 pj[4];
#pragma unroll
                for (int t = 0; t < 4; ++t) pj[t] = s_tab[jj[t]];
                float res[4];
#pragma unroll
                for (int t = 0; t < 4; ++t) {
                    float dx = pj[t].x - piA.x;
                    float dy = pj[t].y - piA.y;
                    float dz = pj[t].z - piA.z;
                    dx = fmaf(ox[t], c00, fmaf(oy[t], c10, fmaf(oz[t], c20, dx)));
                    dy = fmaf(ox[t], c01, fmaf(oy[t], c11, fmaf(oz[t], c21, dy)));
                    dz = fmaf(ox[t], c02, fmaf(oy[t], c12, fmaf(oz[t], c22, dz)));
                    res[t] = (mm[t] > 0.0f)
                           ? sqrtf(fmaf(dx, dx, fmaf(dy, dy, dz * dz))) : 0.0f;
                }
                __stcs((float4*)(out + baseA),
                       make_float4(res[0], res[1], res[2], res[3]));
            }
            // --- row B ---
            {
                const int   jj[4] = { nbB.x, nbB.y, nbB.z, nbB.w };
                const float ox[4] = { b0.x, b0.w, b1.z, b2.y };
                const float oy[4] = { b0.y, b1.x, b1.w, b2.z };
                const float oz[4] = { b0.z, b1.y, b2.x, b2.w };
                const float mm[4] = { mkB.x, mkB.y, mkB.z, mkB.w };
                float4 pj[4];
#pragma unroll
                for (int t = 0; t < 4; ++t) pj[t] = s_tab[jj[t]];
                float res[4];
#pragma unroll
                for (int t = 0; t < 4; ++t) {
                    float dx = pj[t].x - piB.x;
                    float dy = pj[t].y - piB.y;
                    float dz = pj[t].z - piB.z;
                    dx = fmaf(ox[t], c00, fmaf(oy[t], c10, fmaf(oz[t], c20, dx)));
                    dy = fmaf(ox[t], c01, fmaf(oy[t], c11, fmaf(oz[t], c21, dy)));
                    dz = fmaf(ox[t], c02, fmaf(oy[t], c12, fmaf(oz[t], c22, dz)));
                    res[t] = (mm[t] > 0.0f)
                           ? sqrtf(fmaf(dx, dx, fmaf(dy, dy, dz * dz))) : 0.0f;
                }
                __stcs((float4*)(out + baseB),
                       make_float4(res[0], res[1], res[2], res[3]));
            }
        }
        // --- odd tail row ---
        if (r < r1) {
            const long base = ((long)b * N + r) * 128 + lane * 4;
            const int4   nb4 = __ldcs((const int4*)  (neighbors + base));
            const float4 mk4 = __ldcs((const float4*)(mask      + base));
            const float* offp = offsets + base * 3;
            const float4 o0 = __ldcs((const float4*)(offp + 0));
            const float4 o1 = __ldcs((const float4*)(offp + 4));
            const float4 o2 = __ldcs((const float4*)(offp + 8));
            const float4 pi4 = s_tab[r];
            const int   jj[4] = { nb4.x, nb4.y, nb4.z, nb4.w };
            const float ox[4] = { o0.x, o0.w, o1.z, o2.y };
            const float oy[4] = { o0.y, o1.x, o1.w, o2.z };
            const float oz[4] = { o0.z, o1.y, o2.x, o2.w };
            const float mm[4] = { mk4.x, mk4.y, mk4.z, mk4.w };
            float4 pj[4];
#pragma unroll
            for (int t = 0; t < 4; ++t) pj[t] = s_tab[jj[t]];
            float res[4];
#pragma unroll
            for (int t = 0; t < 4; ++t) {
                float dx = pj[t].x - pi4.x;
                float dy = pj[t].y - pi4.y;
                float dz = pj[t].z - pi4.z;
                dx = fmaf(ox[t], c00, fmaf(oy[t], c10, fmaf(oz[t], c20, dx)));
                dy = fmaf(ox[t], c01, fmaf(oy[t], c11, fmaf(oz[t], c21, dy)));
                dz = fmaf(ox[t], c02, fmaf(oy[t], c12, fmaf(oz[t], c22, dz)));
                res[t] = (mm[t] > 0.0f)
                       ? sqrtf(fmaf(dx, dx, fmaf(dy, dy, dz * dz))) : 0.0f;
            }
            __stcs((float4*)(out + base),
                   make_float4(res[0], res[1], res[2], res[3]));
        }
        return;
    }

    // Generic K path (shape variants).
    for (int r = r0 + warp; r < r1; r += n_warps) {
        const float4 pi4 = s_tab[r];
        for (int k0 = lane * 4; k0 < K; k0 += 128) {
            const long base = ((long)b * N + r) * (long)K + k0;
            const int4   nb4 = __ldcs((const int4*)  (neighbors + base));
            const float4 mk4 = __ldcs((const float4*)(mask      + base));
            const float* offp = offsets + base * 3;
            const float4 o0 = __ldcs((const float4*)(offp + 0));
            const float4 o1 = __ldcs((const float4*)(offp + 4));
            const float4 o2 = __ldcs((const float4*)(offp + 8));
            const int   jj[4] = { nb4.x, nb4.y, nb4.z, nb4.w };
            const float ox[4] = { o0.x, o0.w, o1.z, o2.y };
            const float oy[4] = { o0.y, o1.x, o1.w, o2.z };
            const float oz[4] = { o0.z, o1.y, o2.x, o2.w };
            const float mm[4] = { mk4.x, mk4.y, mk4.z, mk4.w };
            float4 pj[4];
#pragma unroll
            for (int t = 0; t < 4; ++t) pj[t] = s_tab[jj[t]];
            float res[4];
#pragma unroll
            for (int t = 0; t < 4; ++t) {
                float dx = pj[t].x - pi4.x;
                float dy = pj[t].y - pi4.y;
                float dz = pj[t].z - pi4.z;
                dx = fmaf(ox[t], c00, fmaf(oy[t], c10, fmaf(oz[t], c20, dx)));
                dy = fmaf(ox[t], c01, fmaf(oy[t], c11, fmaf(oz[t], c21, dy)));
                dz = fmaf(ox[t], c02, fmaf(oy[t], c12, fmaf(oz[t], c22, dz)));
                res[t] = (mm[t] > 0.0f)
                       ? sqrtf(fmaf(dx, dx, fmaf(dy, dy, dz * dz))) : 0.0f;
            }
            __stcs((float4*)(out + base),
                   make_float4(res[0], res[1], res[2], res[3]));
        }
    }
}

// ---------------- fallback (global-gather) for oversized N ----------------
__global__ __launch_bounds__(256)
void pairwise_dist_kernel(const int*    __restrict__ neighbors,
                          const float*  __restrict__ mask,
                          const float*  __restrict__ cell,
                          const float*  __restrict__ offsets,
                          float*        __restrict__ out,
                          int N, int K, int n_rows)
{
    const int warp = threadIdx.x >> 5;
    const int lane = threadIdx.x & 31;
    const int row  = blockIdx.x * 8 + warp;
    if (row >= n_rows) return;
    const int b = row / N;

    const float4 pi4 = __ldg(&g_pos4[row]);
    const float* cb = cell + b * 9;
    const float c00 = __ldg(&cb[0]), c01 = __ldg(&cb[1]), c02 = __ldg(&cb[2]);
    const float c10 = __ldg(&cb[3]), c11 = __ldg(&cb[4]), c12 = __ldg(&cb[5]);
    const float c20 = __ldg(&cb[6]), c21 = __ldg(&cb[7]), c22 = __ldg(&cb[8]);

    for (int k0 = lane * 4; k0 < K; k0 += 128) {
        const long base = (long)row * K + k0;
        const int4   nb4 = __ldcs((const int4*)  (neighbors + base));
        const float4 mk4 = __ldcs((const float4*)(mask      + base));
        const float* offp = offsets + base * 3;
        const float4 o0 = __ldcs((const float4*)(offp + 0));
        const float4 o1 = __ldcs((const float4*)(offp + 4));
        const float4 o2 = __ldcs((const float4*)(offp + 8));

        const float ox[4] = { o0.x, o0.w, o1.z, o2.y };
        const float oy[4] = { o0.y, o1.x, o1.w, o2.z };
        const float oz[4] = { o0.z, o1.y, o2.x, o2.w };
        const int   jj[4] = { nb4.x, nb4.y, nb4.z, nb4.w };
        const float mm[4] = { mk4.x, mk4.y, mk4.z, mk4.w };

        const float4* posb4 = g_pos4 + (long)b * N;
        float4 pj[4];
#pragma unroll
        for (int t = 0; t < 4; ++t) pj[t] = __ldg(&posb4[jj[t]]);

        float res[4];
#pragma unroll
        for (int t = 0; t < 4; ++t) {
            float dx = pj[t].x - pi4.x;
            float dy = pj[t].y - pi4.y;
            float dz = pj[t].z - pi4.z;
            dx = fmaf(ox[t], c00, fmaf(oy[t], c10, fmaf(oz[t], c20, dx)));
            dy = fmaf(ox[t], c01, fmaf(oy[t], c11, fmaf(oz[t], c21, dy)));
            dz = fmaf(ox[t], c02, fmaf(oy[t], c12, fmaf(oz[t], c22, dz)));
            res[t] = (mm[t] > 0.0f) ? sqrtf(fmaf(dx, dx, fmaf(dy, dy, dz * dz))) : 0.0f;
        }
        __stcs((float4*)(out + base), make_float4(res[0], res[1], res[2], res[3]));
    }
}

extern "C" void kernel_launch(void* const* d_in, const int* in_sizes, int n_in,
                              void* d_out, int out_size)
{
    const float* positions = (const float*)d_in[0];
    const int*   neighbors = (const int*)  d_in[1];
    const float* mask      = (const float*)d_in[2];
    const float* cell      = (const float*)d_in[3];
    const float* offsets   = (const float*)d_in[4];
    float*       out       = (float*)d_out;

    const int B      = in_sizes[3] / 9;
    const int n_rows = in_sizes[0] / 3;      // B*N
    const int N      = n_rows / B;
    const int K      = in_sizes[1] / n_rows;

    const size_t smem = (size_t)N * sizeof(float4);

    if (smem <= 65536) {
        static bool attr_set = false;
        if (!attr_set) {
            cudaFuncSetAttribute(pairwise_smem_kernel,
                                 cudaFuncAttributeMaxDynamicSharedMemorySize, 65536);
            attr_set = true;
        }
        // 3 CTAs/SM * 148 SMs = 444 target; S CTAs per batch.
        int S = 444 / B; if (S < 1) S = 1;
        const int rowsPer = (N + S - 1) / S;
        dim3 grid(S, B);
        pairwise_smem_kernel<<<grid, 256, smem>>>(positions, neighbors, mask,
                                                  cell, offsets, out, N, K, rowsPer);
    } else {
        pad_positions_kernel<<<(n_rows + 255) / 256, 256>>>(positions, n_rows);
        const int grid = (n_rows + 7) / 8;
        pairwise_dist_kernel<<<grid, 256>>>(neighbors, mask, cell,
                                            offsets, out, N, K, n_rows);
    }
}